// round 13
// baseline (speedup 1.0000x reference)
#include <cuda_runtime.h>
#include <cuda_bf16.h>

// ApproxEMD: B=16, N=2048, D=3. Flash-style, fused, x-sorted, fine-grained
// exact underflow skipping + PDL (programmatic dependent launch) chaining:
// every kernel fires griddepcontrol.launch_dependents at entry and
// griddepcontrol.wait before reading predecessor data, hiding the per-launch
// scheduling ramp of the 20-kernel dependent chain.
// Tile skip: both point sets x-sorted; per (warp, 32-col tile) the bound
// efl*gap(x)^2 < -150 proves every exp2 underflows to exactly +0.0f (same as
// the fp32 reference), so the tile is skipped with one uniform branch.

#define BB 16
#define NN 2048
#define BN (BB*NN)
#define EPSV 1e-9f
#define CH 128            // rows/cols per smem chunk
#define NCHUNK (NN/CH)    // 16
#define UTH (-150.0f)

#define PDL_FIRE() asm volatile("griddepcontrol.launch_dependents;")
#define PDL_WAIT() asm volatile("griddepcontrol.wait;")

// permuted (x-sorted) copies, SoA
__device__ float g_spx[BN], g_spy[BN], g_spz[BN], g_spn[BN];   // preds
__device__ float g_slx[BN], g_sly[BN], g_slz[BN], g_slm[BN];   // labels
__device__ float g_curr2[2][BN];
__device__ float g_cost2[2][BN];
__device__ float g_SEp[NCHUNK][BN];
__device__ float g_SECp[NCHUNK][BN];
__device__ float g_Rp[NCHUNK][BN];
__device__ double g_out;

typedef unsigned long long u64;

__device__ __forceinline__ float ex2f(float x) {
    float r;
    asm("ex2.approx.f32 %0, %1;" : "=f"(r) : "f"(x));
    return r;
}
__device__ __forceinline__ u64 pk(float lo, float hi) {
    u64 d;
    asm("mov.b64 %0, {%1, %2};" : "=l"(d)
        : "r"(__float_as_uint(lo)), "r"(__float_as_uint(hi)));
    return d;
}
__device__ __forceinline__ void upk(u64 v, float& lo, float& hi) {
    unsigned a, b;
    asm("mov.b64 {%0, %1}, %2;" : "=r"(a), "=r"(b) : "l"(v));
    lo = __uint_as_float(a); hi = __uint_as_float(b);
}
__device__ __forceinline__ u64 fma2(u64 a, u64 b, u64 c) {
    u64 d;
    asm("fma.rn.f32x2 %0, %1, %2, %3;" : "=l"(d) : "l"(a), "l"(b), "l"(c));
    return d;
}
__device__ __forceinline__ u64 add2(u64 a, u64 b) {
    u64 d;
    asm("add.rn.f32x2 %0, %1, %2;" : "=l"(d) : "l"(a), "l"(b));
    return d;
}
__device__ __forceinline__ u64 mul2(u64 a, u64 b) {
    u64 d;
    asm("mul.rn.f32x2 %0, %1, %2;" : "=l"(d) : "l"(a), "l"(b));
    return d;
}

// Bitonic sort by x per (side, batch); gather into SoA + init state.
__global__ void __launch_bounds__(1024) k_sort(
    const float* __restrict__ preds, const float* __restrict__ labels) {
    PDL_FIRE();
    const int side = blockIdx.x;       // 0 = preds, 1 = labels
    const int b = blockIdx.y;
    const float* src = side ? labels : preds;
    __shared__ u64 s[NN];
    const int tid = threadIdx.x;
    PDL_WAIT();

    for (int i = tid; i < NN; i += 1024) {
        float x = src[((size_t)b * NN + i) * 3];
        unsigned u = __float_as_uint(x);
        u = (u & 0x80000000u) ? ~u : (u | 0x80000000u);  // orderable transform
        s[i] = ((u64)u << 32) | (unsigned)i;
    }
    for (int k = 2; k <= NN; k <<= 1) {
        for (int j = k >> 1; j > 0; j >>= 1) {
            __syncthreads();
            for (int i = tid; i < NN; i += 1024) {
                int ixj = i ^ j;
                if (ixj > i) {
                    bool up = ((i & k) == 0);
                    u64 a = s[i], c = s[ixj];
                    if ((a > c) == up) { s[i] = c; s[ixj] = a; }
                }
            }
        }
    }
    __syncthreads();
    for (int i = tid; i < NN; i += 1024) {
        int idx = (int)(s[i] & 0xFFFFFFFFu);
        const float* q = src + ((size_t)b * NN + idx) * 3;
        float x = q[0], y = q[1], z = q[2];
        int o = b * NN + i;
        if (side) {
            g_slx[o] = x; g_sly[o] = y; g_slz[o] = z;
            g_slm[o] = x*x + y*y + z*z;
            g_cost2[0][o] = 1.0f;
        } else {
            g_spx[o] = x; g_spy[o] = y; g_spz[o] = z;
            g_spn[o] = x*x + y*y + z*z;
            g_curr2[0][o] = 1.0f;
#pragma unroll
            for (int ch = 0; ch < NCHUNK; ch++) g_Rp[ch][o] = 0.0f;
        }
    }
    if (side == 0 && b == 0 && tid == 0) g_out = 0.0;
}

// colpass: fused currency update + column sums, per-(warp,ctile) skip.
// grid (NCHUNK, 2, BB), block 256 (8 warps x 4 ctiles of 32 cols).
__global__ void __launch_bounds__(256) k_colpass(float efl, int par) {
    PDL_FIRE();
    const int b = blockIdx.z;
    const int chunk = blockIdx.x;
    __shared__ ulonglong2 sP1[CH/2];  // (m2*px pair, m2*py pair)
    __shared__ ulonglong2 sP2[CH/2];  // (m2*pz pair, wn pair)
    __shared__ u64        sC [CH/2];  // currency pair
    const float m2 = -2.0f * efl;
    PDL_WAIT();

    if (threadIdx.x < CH) {
        const int j = threadIdx.x;
        const int n = b * NN + chunk * CH + j;
        float r = 0.0f;
#pragma unroll
        for (int ch = 0; ch < NCHUNK; ch++) r += g_Rp[ch][n];
        float cu = g_curr2[par][n];
        float c = fmaxf(cu - cu * r, 0.0f);
        g_curr2[1 - par][n] = c;     // duplicate identical write across halves
        // write packed halves directly
        float* p1 = (float*)sP1; float* p2 = (float*)sP2; float* pc = (float*)sC;
        int q = j >> 1, h = j & 1;
        p1[q * 4 + h]     = m2 * g_spx[n];
        p1[q * 4 + 2 + h] = m2 * g_spy[n];
        p2[q * 4 + h]     = m2 * g_spz[n];
        p2[q * 4 + 2 + h] = efl * g_spn[n];
        pc[q * 2 + h]     = c;
    }
    __syncthreads();

    const int lane = threadIdx.x & 31;
    const int w = threadIdx.x >> 5;
    const int rb = b * NN + chunk * CH;
    const float rlo = g_spx[rb], rhi = g_spx[rb + CH - 1];

#pragma unroll
    for (int k = 0; k < 4; k++) {
        const int t = w + 8 * blockIdx.y + 16 * k;    // ctile 0..63
        const int cb = b * NN + t * 32;
        const int m = cb + lane;
        float clo = g_slx[cb], chi = g_slx[cb + 31];
        float gap = fmaxf(0.0f, fmaxf(rlo - chi, clo - rhi));
        float e0 = 0, e1 = 0, c0 = 0, c1 = 0;
        if (efl * gap * gap >= UTH) {                 // else all E == +0.0f
            const u64 lxb = pk(g_slx[m], g_slx[m]);
            const u64 lyb = pk(g_sly[m], g_sly[m]);
            const u64 lzb = pk(g_slz[m], g_slz[m]);
            const float wb = efl * g_slm[m];
            const u64 wbb = pk(wb, wb);
            u64 sE = 0ull, sEC = 0ull;
#pragma unroll 8
            for (int i = 0; i < CH / 2; i++) {
                ulonglong2 A = sP1[i];
                ulonglong2 Bv = sP2[i];
                u64 cc = sC[i];
                u64 arg = fma2(Bv.x, lzb, fma2(A.y, lyb, fma2(A.x, lxb, add2(Bv.y, wbb))));
                float a0, a1; upk(arg, a0, a1);
                u64 e = pk(ex2f(a0), ex2f(a1));
                sE = add2(sE, e);
                sEC = fma2(e, cc, sEC);
            }
            upk(sE, e0, e1); upk(sEC, c0, c1);
        }
        g_SEp [chunk][m] = e0 + e1;
        g_SECp[chunk][m] = c0 + c1;
    }
}

// rowpass: fused g/cost update + row sums + out, per-(warp,rtile) skip.
// grid (NCHUNK, 2, BB), block 256. chunk indexes LABEL columns here.
__global__ void __launch_bounds__(256) k_rowpass(float efl, float inv_efl, int par) {
    PDL_FIRE();
    const int b = blockIdx.z;
    const int chunk = blockIdx.x;
    __shared__ ulonglong2 sL1[CH/2];  // (m2*lx pair, m2*ly pair)
    __shared__ ulonglong2 sL2[CH/2];  // (m2*lz pair, wl pair)
    __shared__ u64        sG [CH/2];  // g pair
    __shared__ float      sred[8];
    const float m2 = -2.0f * efl;
    PDL_WAIT();

    if (threadIdx.x < CH) {
        const int j = threadIdx.x;
        const int m = b * NN + chunk * CH + j;
        float se = 0.0f, sec = 0.0f;
#pragma unroll
        for (int ch = 0; ch < NCHUNK; ch++) {
            se += g_SEp[ch][m];
            sec += g_SECp[ch][m];
        }
        float cost = g_cost2[par][m];
        float s1 = cost * se;
        float s2 = cost * sec / (s1 + EPSV);
        float wt = fminf(cost / (s2 + EPSV), 1.0f);
        float gv = cost * wt / (s1 + EPSV);
        g_cost2[1 - par][m] = fmaxf(cost - s2 * wt, 0.0f);  // dup identical write
        float* p1 = (float*)sL1; float* p2 = (float*)sL2; float* pg = (float*)sG;
        int q = j >> 1, h = j & 1;
        p1[q * 4 + h]     = m2 * g_slx[m];
        p1[q * 4 + 2 + h] = m2 * g_sly[m];
        p2[q * 4 + h]     = m2 * g_slz[m];
        p2[q * 4 + 2 + h] = efl * g_slm[m];
        pg[q * 2 + h]     = gv;
    }
    __syncthreads();

    const int lane = threadIdx.x & 31;
    const int w = threadIdx.x >> 5;
    const int cb = b * NN + chunk * CH;
    const float clo = g_slx[cb], chi = g_slx[cb + CH - 1];
    const float* cu = g_curr2[1 - par];

    float v = 0.0f;
#pragma unroll
    for (int k = 0; k < 4; k++) {
        const int t = w + 8 * blockIdx.y + 16 * k;    // pred tile 0..63
        const int pb = b * NN + t * 32;
        const int n = pb + lane;
        float rlo = g_spx[pb], rhi = g_spx[pb + 31];
        float gap = fmaxf(0.0f, fmaxf(rlo - chi, clo - rhi));
        float rsum = 0.0f;
        if (efl * gap * gap >= UTH) {
            const u64 pxb = pk(g_spx[n], g_spx[n]);
            const u64 pyb = pk(g_spy[n], g_spy[n]);
            const u64 pzb = pk(g_spz[n], g_spz[n]);
            const float wp = efl * g_spn[n];
            const u64 wpb = pk(wp, wp);
            u64 rAcc = 0ull, oAcc = 0ull;
#pragma unroll 8
            for (int i = 0; i < CH / 2; i++) {
                ulonglong2 A = sL1[i];
                ulonglong2 Bv = sL2[i];
                u64 g2 = sG[i];
                u64 arg = fma2(Bv.x, pzb, fma2(A.y, pyb, fma2(A.x, pxb, add2(Bv.y, wpb))));
                float a0, a1; upk(arg, a0, a1);
                u64 e = pk(ex2f(a0), ex2f(a1));
                u64 tt = mul2(e, g2);
                rAcc = add2(rAcc, tt);
                oAcc = fma2(tt, arg, oAcc);   // accumulates efl * t * d
            }
            float r0, r1, o0, o1;
            upk(rAcc, r0, r1); upk(oAcc, o0, o1);
            rsum = r0 + r1;
            v += cu[n] * (o0 + o1);
        }
        g_Rp[chunk][n] = rsum;
    }

    v *= inv_efl;
#pragma unroll
    for (int off = 16; off > 0; off >>= 1)
        v += __shfl_down_sync(0xFFFFFFFFu, v, off);
    if (lane == 0) sred[w] = v;
    __syncthreads();
    if (threadIdx.x == 0) {
        float s = 0.0f;
#pragma unroll
        for (int i = 0; i < 8; i++) s += sred[i];
        atomicAdd(&g_out, (double)s);
    }
}

// Last step (ef==0): E==1 everywhere -> closed form O(N) per batch.
__global__ void __launch_bounds__(256) k_ef0() {
    PDL_FIRE();
    const int b = blockIdx.x;
    const int tid = threadIdx.x;
    __shared__ float red[256];
    PDL_WAIT();

    float C = 0, CP = 0, CX = 0, CY = 0, CZ = 0;
    for (int n = tid; n < NN; n += 256) {
        int idx = b * NN + n;
        float r = 0.0f;
#pragma unroll
        for (int ch = 0; ch < NCHUNK; ch++) r += g_Rp[ch][idx];
        float cu = g_curr2[1][idx];
        float c = fmaxf(cu - cu * r, 0.0f);
        C += c; CP += c * g_spn[idx];
        CX += c * g_spx[idx]; CY += c * g_spy[idx]; CZ += c * g_spz[idx];
    }
    auto reduce = [&](float v) -> float {
        red[tid] = v; __syncthreads();
        for (int s = 128; s > 0; s >>= 1) {
            if (tid < s) red[tid] += red[tid + s];
            __syncthreads();
        }
        float r = red[0]; __syncthreads();
        return r;
    };
    float Cs = reduce(C);
    float CPs = reduce(CP);
    float CXs = reduce(CX);
    float CYs = reduce(CY);
    float CZs = reduce(CZ);

    float G = 0, GL = 0, GX = 0, GY = 0, GZ = 0;
    for (int m = tid; m < NN; m += 256) {
        int idx = b * NN + m;
        float cost = g_cost2[1][idx];   // cost after step 8
        float s1 = cost * (float)NN;
        float s2 = cost * Cs / (s1 + EPSV);
        float wt = fminf(cost / (s2 + EPSV), 1.0f);
        float g = cost * wt / (s1 + EPSV);
        G += g; GL += g * g_slm[idx];
        GX += g * g_slx[idx]; GY += g * g_sly[idx]; GZ += g * g_slz[idx];
    }
    float Gs = reduce(G);
    float GLs = reduce(GL);
    float GXs = reduce(GX);
    float GYs = reduce(GY);
    float GZs = reduce(GZ);

    if (tid == 0) {
        double ob = (double)CPs * Gs + (double)Cs * GLs
                  - 2.0 * ((double)CXs * GXs + (double)CYs * GYs + (double)CZs * GZs);
        atomicAdd(&g_out, ob);
    }
}

__global__ void k_write(float* out) {
    PDL_FIRE();
    PDL_WAIT();
    out[0] = (float)g_out;
}

extern "C" void kernel_launch(void* const* d_in, const int* in_sizes, int n_in,
                              void* d_out, int out_size) {
    const float* preds = (const float*)d_in[0];
    const float* labels = (const float*)d_in[1];
    float* out = (float*)d_out;

    static const float EF[9] = {
        -16384.0f, -4096.0f, -1024.0f, -256.0f, -64.0f,
        -16.0f, -4.0f, -1.0f, -0.25f
    };
    const float L2E = 1.4426950408889634f;

    cudaLaunchAttribute attrs[1];
    attrs[0].id = cudaLaunchAttributeProgrammaticStreamSerialization;
    attrs[0].val.programmaticStreamSerializationAllowed = 1;

    cudaLaunchConfig_t cfg = {};
    cfg.attrs = attrs;
    cfg.numAttrs = 1;
    cfg.stream = 0;

    cfg.gridDim = dim3(2, BB);
    cfg.blockDim = dim3(1024);
    cudaLaunchKernelEx(&cfg, k_sort, preds, labels);

    cfg.gridDim = dim3(NCHUNK, 2, BB);   // 512 blocks of 256 threads
    cfg.blockDim = dim3(256);
    for (int s = 0; s < 9; s++) {
        float efl = EF[s] * L2E;
        float inv = 1.0f / efl;
        int par = s & 1;
        cudaLaunchKernelEx(&cfg, k_colpass, efl, par);
        cudaLaunchKernelEx(&cfg, k_rowpass, efl, inv, par);
    }

    cfg.gridDim = dim3(BB);
    cfg.blockDim = dim3(256);
    cudaLaunchKernelEx(&cfg, k_ef0);

    cfg.gridDim = dim3(1);
    cfg.blockDim = dim3(1);
    cudaLaunchKernelEx(&cfg, k_write, out);
}

// round 14
// speedup vs baseline: 1.6323x; 1.6323x over previous
#include <cuda_runtime.h>
#include <cuda_bf16.h>

// ApproxEMD: B=16, N=2048, D=3. Flash-style, fused, x-sorted, fine-grained
// exact underflow skipping, ONE persistent kernel for all 9 auction steps.
// 512 blocks x 256 threads, __launch_bounds__(256,4): all blocks co-resident
// (512 <= 148*4), so a sense-reversing software grid barrier separates the
// col/row phases in-kernel (18 barriers) and all inter-kernel launch gaps
// vanish. Phase bodies identical to the best 458us version (R11).
// Tile skip: both sets x-sorted; per (warp, 32-col tile) efl*gap(x)^2 < -150
// proves every exp2 underflows to exactly +0.0f (matches fp32 reference).

#define BB 16
#define NN 2048
#define BN (BB*NN)
#define EPSV 1e-9f
#define CH 128            // rows/cols per smem chunk
#define NCHUNK (NN/CH)    // 16
#define UTH (-150.0f)
#define NBLK 512

// permuted (x-sorted) copies, SoA
__device__ float g_spx[BN], g_spy[BN], g_spz[BN], g_spn[BN];   // preds
__device__ float g_slx[BN], g_sly[BN], g_slz[BN], g_slm[BN];   // labels
__device__ float g_curr2[2][BN];
__device__ float g_cost2[2][BN];
__device__ float g_SEp[NCHUNK][BN];
__device__ float g_SECp[NCHUNK][BN];
__device__ float g_Rp[NCHUNK][BN];
__device__ double g_out;
__device__ unsigned g_bar_count;   // zero-init
__device__ unsigned g_bar_gen;     // zero-init; monotonic across replays

__constant__ float c_EFL[9] = {   // ef * log2(e)
    -16384.0f * 1.4426950408889634f, -4096.0f * 1.4426950408889634f,
    -1024.0f * 1.4426950408889634f,  -256.0f * 1.4426950408889634f,
    -64.0f * 1.4426950408889634f,    -16.0f * 1.4426950408889634f,
    -4.0f * 1.4426950408889634f,     -1.0f * 1.4426950408889634f,
    -0.25f * 1.4426950408889634f
};

typedef unsigned long long u64;

__device__ __forceinline__ float ex2f(float x) {
    float r;
    asm("ex2.approx.f32 %0, %1;" : "=f"(r) : "f"(x));
    return r;
}
__device__ __forceinline__ u64 pk(float lo, float hi) {
    u64 d;
    asm("mov.b64 %0, {%1, %2};" : "=l"(d)
        : "r"(__float_as_uint(lo)), "r"(__float_as_uint(hi)));
    return d;
}
__device__ __forceinline__ void upk(u64 v, float& lo, float& hi) {
    unsigned a, b;
    asm("mov.b64 {%0, %1}, %2;" : "=r"(a), "=r"(b) : "l"(v));
    lo = __uint_as_float(a); hi = __uint_as_float(b);
}
__device__ __forceinline__ u64 fma2(u64 a, u64 b, u64 c) {
    u64 d;
    asm("fma.rn.f32x2 %0, %1, %2, %3;" : "=l"(d) : "l"(a), "l"(b), "l"(c));
    return d;
}
__device__ __forceinline__ u64 add2(u64 a, u64 b) {
    u64 d;
    asm("add.rn.f32x2 %0, %1, %2;" : "=l"(d) : "l"(a), "l"(b));
    return d;
}
__device__ __forceinline__ u64 mul2(u64 a, u64 b) {
    u64 d;
    asm("mul.rn.f32x2 %0, %1, %2;" : "=l"(d) : "l"(a), "l"(b));
    return d;
}

// Software grid barrier: valid because all NBLK blocks are co-resident.
__device__ __forceinline__ void grid_sync() {
    __syncthreads();
    if (threadIdx.x == 0) {
        __threadfence();
        unsigned gen = *(volatile unsigned*)&g_bar_gen;
        if (atomicAdd(&g_bar_count, 1u) == NBLK - 1u) {
            g_bar_count = 0;
            __threadfence();
            *(volatile unsigned*)&g_bar_gen = gen + 1u;
        } else {
            while (*(volatile unsigned*)&g_bar_gen == gen) __nanosleep(64);
        }
        __threadfence();
    }
    __syncthreads();
}

// Bitonic sort by x per (side, batch); gather into SoA + init state.
__global__ void __launch_bounds__(1024) k_sort(
    const float* __restrict__ preds, const float* __restrict__ labels) {
    const int side = blockIdx.x;       // 0 = preds, 1 = labels
    const int b = blockIdx.y;
    const float* src = side ? labels : preds;
    __shared__ u64 s[NN];
    const int tid = threadIdx.x;

    for (int i = tid; i < NN; i += 1024) {
        float x = src[((size_t)b * NN + i) * 3];
        unsigned u = __float_as_uint(x);
        u = (u & 0x80000000u) ? ~u : (u | 0x80000000u);  // orderable transform
        s[i] = ((u64)u << 32) | (unsigned)i;
    }
    for (int k = 2; k <= NN; k <<= 1) {
        for (int j = k >> 1; j > 0; j >>= 1) {
            __syncthreads();
            for (int i = tid; i < NN; i += 1024) {
                int ixj = i ^ j;
                if (ixj > i) {
                    bool up = ((i & k) == 0);
                    u64 a = s[i], c = s[ixj];
                    if ((a > c) == up) { s[i] = c; s[ixj] = a; }
                }
            }
        }
    }
    __syncthreads();
    for (int i = tid; i < NN; i += 1024) {
        int idx = (int)(s[i] & 0xFFFFFFFFu);
        const float* q = src + ((size_t)b * NN + idx) * 3;
        float x = q[0], y = q[1], z = q[2];
        int o = b * NN + i;
        if (side) {
            g_slx[o] = x; g_sly[o] = y; g_slz[o] = z;
            g_slm[o] = x*x + y*y + z*z;
            g_cost2[0][o] = 1.0f;
        } else {
            g_spx[o] = x; g_spy[o] = y; g_spz[o] = z;
            g_spn[o] = x*x + y*y + z*z;
            g_curr2[0][o] = 1.0f;
#pragma unroll
            for (int ch = 0; ch < NCHUNK; ch++) g_Rp[ch][o] = 0.0f;
        }
    }
    if (side == 0 && b == 0 && tid == 0) g_out = 0.0;
}

// Persistent kernel: all 9 steps + ef0 closed form.
// grid (NCHUNK, 2, BB) = 512 blocks, 256 threads.
__global__ void __launch_bounds__(256, 4) k_persist() {
    const int b = blockIdx.z;
    const int chunk = blockIdx.x;
    const int half = blockIdx.y;
    __shared__ ulonglong2 sD1[CH/2];  // (m2*vx pair, m2*vy pair)
    __shared__ ulonglong2 sD2[CH/2];  // (m2*vz pair, w pair)
    __shared__ u64        sS [CH/2];  // scalar pair (currency or g)
    __shared__ float      sred[256];

    const int lane = threadIdx.x & 31;
    const int w = threadIdx.x >> 5;

    for (int s = 0; s < 9; s++) {
        const float efl = c_EFL[s];
        const float m2 = -2.0f * efl;
        const int par = s & 1;

        // ---------------- col phase ----------------
        if (threadIdx.x < CH) {
            const int j = threadIdx.x;
            const int n = b * NN + chunk * CH + j;
            float r = 0.0f;
#pragma unroll
            for (int ch = 0; ch < NCHUNK; ch++) r += g_Rp[ch][n];
            float cu = g_curr2[par][n];
            float c = fmaxf(cu - cu * r, 0.0f);
            g_curr2[1 - par][n] = c;   // duplicate identical write across halves
            float* p1 = (float*)sD1; float* p2 = (float*)sD2; float* pc = (float*)sS;
            int q = j >> 1, h = j & 1;
            p1[q * 4 + h]     = m2 * g_spx[n];
            p1[q * 4 + 2 + h] = m2 * g_spy[n];
            p2[q * 4 + h]     = m2 * g_spz[n];
            p2[q * 4 + 2 + h] = efl * g_spn[n];
            pc[q * 2 + h]     = c;
        }
        __syncthreads();

        {
            const int rb = b * NN + chunk * CH;
            const float rlo = g_spx[rb], rhi = g_spx[rb + CH - 1];
#pragma unroll
            for (int k = 0; k < 4; k++) {
                const int t = w + 8 * half + 16 * k;      // ctile 0..63
                const int cb = b * NN + t * 32;
                const int m = cb + lane;
                float clo = g_slx[cb], chi = g_slx[cb + 31];
                float gap = fmaxf(0.0f, fmaxf(rlo - chi, clo - rhi));
                float e0 = 0, e1 = 0, c0 = 0, c1 = 0;
                if (efl * gap * gap >= UTH) {             // else all E == +0.0f
                    const u64 lxb = pk(g_slx[m], g_slx[m]);
                    const u64 lyb = pk(g_sly[m], g_sly[m]);
                    const u64 lzb = pk(g_slz[m], g_slz[m]);
                    const float wb = efl * g_slm[m];
                    const u64 wbb = pk(wb, wb);
                    u64 sE = 0ull, sEC = 0ull;
#pragma unroll 8
                    for (int i = 0; i < CH / 2; i++) {
                        ulonglong2 A = sD1[i];
                        ulonglong2 Bv = sD2[i];
                        u64 cc = sS[i];
                        u64 arg = fma2(Bv.x, lzb, fma2(A.y, lyb,
                                       fma2(A.x, lxb, add2(Bv.y, wbb))));
                        float a0, a1; upk(arg, a0, a1);
                        u64 e = pk(ex2f(a0), ex2f(a1));
                        sE = add2(sE, e);
                        sEC = fma2(e, cc, sEC);
                    }
                    upk(sE, e0, e1); upk(sEC, c0, c1);
                }
                g_SEp [chunk][m] = e0 + e1;
                g_SECp[chunk][m] = c0 + c1;
            }
        }
        grid_sync();

        // ---------------- row phase ----------------
        if (threadIdx.x < CH) {
            const int j = threadIdx.x;
            const int m = b * NN + chunk * CH + j;
            float se = 0.0f, sec = 0.0f;
#pragma unroll
            for (int ch = 0; ch < NCHUNK; ch++) {
                se += g_SEp[ch][m];
                sec += g_SECp[ch][m];
            }
            float cost = g_cost2[par][m];
            float s1 = cost * se;
            float s2 = cost * sec / (s1 + EPSV);
            float wt = fminf(cost / (s2 + EPSV), 1.0f);
            float gv = cost * wt / (s1 + EPSV);
            g_cost2[1 - par][m] = fmaxf(cost - s2 * wt, 0.0f);  // dup write
            float* p1 = (float*)sD1; float* p2 = (float*)sD2; float* pg = (float*)sS;
            int q = j >> 1, h = j & 1;
            p1[q * 4 + h]     = m2 * g_slx[m];
            p1[q * 4 + 2 + h] = m2 * g_sly[m];
            p2[q * 4 + h]     = m2 * g_slz[m];
            p2[q * 4 + 2 + h] = efl * g_slm[m];
            pg[q * 2 + h]     = gv;
        }
        __syncthreads();

        {
            const int cb = b * NN + chunk * CH;
            const float clo = g_slx[cb], chi = g_slx[cb + CH - 1];
            const float* cu = g_curr2[1 - par];
            float v = 0.0f;
#pragma unroll
            for (int k = 0; k < 4; k++) {
                const int t = w + 8 * half + 16 * k;      // pred tile 0..63
                const int pb = b * NN + t * 32;
                const int n = pb + lane;
                float rlo = g_spx[pb], rhi = g_spx[pb + 31];
                float gap = fmaxf(0.0f, fmaxf(rlo - chi, clo - rhi));
                float rsum = 0.0f;
                if (efl * gap * gap >= UTH) {
                    const u64 pxb = pk(g_spx[n], g_spx[n]);
                    const u64 pyb = pk(g_spy[n], g_spy[n]);
                    const u64 pzb = pk(g_spz[n], g_spz[n]);
                    const float wp = efl * g_spn[n];
                    const u64 wpb = pk(wp, wp);
                    u64 rAcc = 0ull, oAcc = 0ull;
#pragma unroll 8
                    for (int i = 0; i < CH / 2; i++) {
                        ulonglong2 A = sD1[i];
                        ulonglong2 Bv = sD2[i];
                        u64 g2 = sS[i];
                        u64 arg = fma2(Bv.x, pzb, fma2(A.y, pyb,
                                       fma2(A.x, pxb, add2(Bv.y, wpb))));
                        float a0, a1; upk(arg, a0, a1);
                        u64 e = pk(ex2f(a0), ex2f(a1));
                        u64 tt = mul2(e, g2);
                        rAcc = add2(rAcc, tt);
                        oAcc = fma2(tt, arg, oAcc);   // accumulates efl * t * d
                    }
                    float r0, r1, o0, o1;
                    upk(rAcc, r0, r1); upk(oAcc, o0, o1);
                    rsum = r0 + r1;
                    v += cu[n] * (o0 + o1);
                }
                g_Rp[chunk][n] = rsum;
            }
            v *= (1.0f / efl);
#pragma unroll
            for (int off = 16; off > 0; off >>= 1)
                v += __shfl_down_sync(0xFFFFFFFFu, v, off);
            if (lane == 0) sred[w] = v;
            __syncthreads();
            if (threadIdx.x == 0) {
                float sv = 0.0f;
#pragma unroll
                for (int i = 0; i < 8; i++) sv += sred[i];
                atomicAdd(&g_out, (double)sv);
            }
        }
        grid_sync();
    }

    // ---------------- ef==0 step: closed form, one block per batch ----------
    if (chunk == 0 && half == 0) {
        const int tid = threadIdx.x;
        float C = 0, CP = 0, CX = 0, CY = 0, CZ = 0;
        for (int n = tid; n < NN; n += 256) {
            int idx = b * NN + n;
            float r = 0.0f;
#pragma unroll
            for (int ch = 0; ch < NCHUNK; ch++) r += g_Rp[ch][idx];
            float cu = g_curr2[1][idx];
            float c = fmaxf(cu - cu * r, 0.0f);
            C += c; CP += c * g_spn[idx];
            CX += c * g_spx[idx]; CY += c * g_spy[idx]; CZ += c * g_spz[idx];
        }
        auto reduce = [&](float v) -> float {
            sred[tid] = v; __syncthreads();
            for (int st = 128; st > 0; st >>= 1) {
                if (tid < st) sred[tid] += sred[tid + st];
                __syncthreads();
            }
            float r = sred[0]; __syncthreads();
            return r;
        };
        float Cs = reduce(C);
        float CPs = reduce(CP);
        float CXs = reduce(CX);
        float CYs = reduce(CY);
        float CZs = reduce(CZ);

        float G = 0, GL = 0, GX = 0, GY = 0, GZ = 0;
        for (int m = tid; m < NN; m += 256) {
            int idx = b * NN + m;
            float cost = g_cost2[1][idx];   // cost after step 8
            float s1 = cost * (float)NN;
            float s2 = cost * Cs / (s1 + EPSV);
            float wt = fminf(cost / (s2 + EPSV), 1.0f);
            float g = cost * wt / (s1 + EPSV);
            G += g; GL += g * g_slm[idx];
            GX += g * g_slx[idx]; GY += g * g_sly[idx]; GZ += g * g_slz[idx];
        }
        float Gs = reduce(G);
        float GLs = reduce(GL);
        float GXs = reduce(GX);
        float GYs = reduce(GY);
        float GZs = reduce(GZ);

        if (tid == 0) {
            double ob = (double)CPs * Gs + (double)Cs * GLs
                      - 2.0 * ((double)CXs * GXs + (double)CYs * GYs + (double)CZs * GZs);
            atomicAdd(&g_out, ob);
        }
    }
}

__global__ void k_write(float* out) {
    out[0] = (float)g_out;
}

extern "C" void kernel_launch(void* const* d_in, const int* in_sizes, int n_in,
                              void* d_out, int out_size) {
    const float* preds = (const float*)d_in[0];
    const float* labels = (const float*)d_in[1];
    float* out = (float*)d_out;

    k_sort<<<dim3(2, BB), 1024>>>(preds, labels);
    k_persist<<<dim3(NCHUNK, 2, BB), 256>>>();   // 512 co-resident blocks
    k_write<<<1, 1>>>(out);
}